// round 2
// baseline (speedup 1.0000x reference)
#include <cuda_runtime.h>
#include <mma.h>
#include <cstdint>

using namespace nvcuda;

// Problem constants
#define S_LEN 2048
#define HID_  4096
#define NQ_   32
#define NKV_  8
#define HD_   128
#define BATCH 2
#define GRP   (NQ_ / NKV_)   // 4 q-heads per kv-head

// ---------------------------------------------------------------------------
// Device scratch (static: no allocations allowed)
// ---------------------------------------------------------------------------
__device__ float g_q [(size_t)BATCH * NQ_  * S_LEN * HD_];   // [B,NQ,S,HD]   64 MB
__device__ float g_k [(size_t)BATCH * NKV_ * S_LEN * HD_];   // [B,NKV,S,HD]  16 MB
__device__ float g_vt[(size_t)BATCH * NKV_ * HD_ * S_LEN];   // [B,NKV,HD,S]  16 MB (V transposed)
__device__ float g_scores[268435456];                        // [B*NQ,S,S]     1 GB
__device__ float g_attn[(size_t)BATCH * S_LEN * NQ_ * HD_];  // [B,S,NQ*HD]   64 MB

// ---------------------------------------------------------------------------
// GEMM config: C[M,N] = A[M,K] * B[N,K]^T   (tf32 tensor cores)
// Block tile 128x128, K-tile 32, 256 threads (8 warps, 2x4), warp tile 64x32
// ---------------------------------------------------------------------------
constexpr int BM = 128, BN = 128, BK = 32;
constexpr int LDS = BK + 4;                 // skew: 36 floats (144B rows, 16B aligned)
constexpr int SMEM_BYTES = (2 * BM * LDS + 2 * BN * LDS) * 4;   // 73728

__device__ __forceinline__ void cp_async16(float* smem_dst, const float* gsrc) {
    uint32_t d = (uint32_t)__cvta_generic_to_shared(smem_dst);
    asm volatile("cp.async.cg.shared.global [%0], [%1], 16;\n" :: "r"(d), "l"(gsrc));
}
__device__ __forceinline__ void cp_commit() { asm volatile("cp.async.commit_group;\n"); }
__device__ __forceinline__ void cp_wait0()  { asm volatile("cp.async.wait_group 0;\n"); }

// MODE 0: Q-proj   A=x[4096,4096]        B=Wq[4096,4096]   -> scatter g_q
// MODE 1: KV-proj  A=x                   B=Wkv[2048,4096]  -> scatter g_k / g_vt (V transposed)
// MODE 2: scores   A=g_q head slice      B=g_k head slice  -> g_scores (causal tiles, scaled)
// MODE 3: PV       A=g_scores head slice B=g_vt head slice -> g_attn
// MODE 4: O-proj   A=g_attn              B=Wo[4096,4096]   -> d_out
template<int MODE>
__global__ void __launch_bounds__(256)
gemm_tf32(const float* __restrict__ Aext, const float* __restrict__ Bext,
          float* __restrict__ Cext, int Kdim)
{
    extern __shared__ float smem[];
    float* As = smem;                      // 2 * BM * LDS
    float* Bs = smem + 2 * BM * LDS;       // 2 * BN * LDS

    int mtile = blockIdx.y;
    int ntile = blockIdx.x;

    if (MODE == 2) {
        // Linearized lower-triangular tile index: blockIdx.x in [0,136)
        // Decode t -> (it, jt) with jt <= it for a 16x16 tile triangle.
        int t = blockIdx.x;
        int it = 0;
        while (t >= it + 1) { t -= it + 1; it++; }
        mtile = it; ntile = t;
    }

    const int m0 = mtile * BM;
    const int n0 = ntile * BN;

    const float* Ap; const float* Bp;
    int lda, ldb;
    int z = 0, bb = 0, hh = 0;

    if (MODE == 0) { Ap = Aext; Bp = Bext; lda = HID_; ldb = HID_; }
    else if (MODE == 1) { Ap = Aext; Bp = Bext; lda = HID_; ldb = HID_; }
    else if (MODE == 2) {
        z = blockIdx.z; bb = z / NQ_; hh = z % NQ_;
        int kvh = hh / GRP;
        Ap = g_q + (size_t)z * S_LEN * HD_;                    lda = HD_;
        Bp = g_k + (size_t)(bb * NKV_ + kvh) * S_LEN * HD_;    ldb = HD_;
    }
    else if (MODE == 3) {
        z = blockIdx.z; bb = z / NQ_; hh = z % NQ_;
        int kvh = hh / GRP;
        Ap = g_scores + (size_t)z * S_LEN * S_LEN;             lda = S_LEN;
        Bp = g_vt + (size_t)(bb * NKV_ + kvh) * HD_ * S_LEN;   ldb = S_LEN;
        Kdim = min(Kdim, (mtile + 1) * BM);                    // causal K-limit
    }
    else { // MODE 4
        Ap = g_attn; Bp = Bext; lda = HID_; ldb = HID_;
    }

    const int tid  = threadIdx.x;
    const int warp = tid >> 5;
    const int wr   = warp >> 2;    // 0..1
    const int wc   = warp & 3;     // 0..3

    wmma::fragment<wmma::accumulator, 16, 16, 8, float> acc[4][2];
    #pragma unroll
    for (int i = 0; i < 4; i++)
        #pragma unroll
        for (int j = 0; j < 2; j++)
            wmma::fill_fragment(acc[i][j], 0.0f);

    auto loadA = [&](int t, int buf) {
        const float* src = Ap + (size_t)m0 * lda + t * BK;
        float* dst = As + buf * BM * LDS;
        #pragma unroll
        for (int i = 0; i < 4; i++) {
            int idx = tid + i * 256;
            int row = idx >> 3, seg = idx & 7;
            cp_async16(dst + row * LDS + seg * 4, src + (size_t)row * lda + seg * 4);
        }
    };
    auto loadB = [&](int t, int buf) {
        const float* src = Bp + (size_t)n0 * ldb + t * BK;
        float* dst = Bs + buf * BN * LDS;
        #pragma unroll
        for (int i = 0; i < 4; i++) {
            int idx = tid + i * 256;
            int row = idx >> 3, seg = idx & 7;
            cp_async16(dst + row * LDS + seg * 4, src + (size_t)row * ldb + seg * 4);
        }
    };

    const int T = Kdim / BK;
    loadA(0, 0); loadB(0, 0); cp_commit();

    for (int t = 0; t < T; t++) {
        cp_wait0();
        __syncthreads();
        if (t + 1 < T) { loadA(t + 1, (t + 1) & 1); loadB(t + 1, (t + 1) & 1); cp_commit(); }

        const float* Ab = As + (t & 1) * BM * LDS;
        const float* Bb = Bs + (t & 1) * BN * LDS;

        #pragma unroll
        for (int kk = 0; kk < BK / 8; kk++) {
            wmma::fragment<wmma::matrix_a, 16, 16, 8, wmma::precision::tf32, wmma::row_major> af[4];
            wmma::fragment<wmma::matrix_b, 16, 16, 8, wmma::precision::tf32, wmma::col_major> bf[2];
            #pragma unroll
            for (int i = 0; i < 4; i++) {
                wmma::load_matrix_sync(af[i], Ab + (wr * 64 + i * 16) * LDS + kk * 8, LDS);
                #pragma unroll
                for (int e = 0; e < af[i].num_elements; e++)
                    af[i].x[e] = wmma::__float_to_tf32(af[i].x[e]);
            }
            #pragma unroll
            for (int j = 0; j < 2; j++) {
                wmma::load_matrix_sync(bf[j], Bb + (wc * 32 + j * 16) * LDS + kk * 8, LDS);
                #pragma unroll
                for (int e = 0; e < bf[j].num_elements; e++)
                    bf[j].x[e] = wmma::__float_to_tf32(bf[j].x[e]);
            }
            #pragma unroll
            for (int i = 0; i < 4; i++)
                #pragma unroll
                for (int j = 0; j < 2; j++)
                    wmma::mma_sync(acc[i][j], af[i], bf[j], acc[i][j]);
        }
        __syncthreads();
    }

    // -------------------- epilogue (per-mode scatter) --------------------
    #pragma unroll
    for (int i = 0; i < 4; i++) {
        #pragma unroll
        for (int j = 0; j < 2; j++) {
            const int gm = m0 + wr * 64 + i * 16;
            const int gn = n0 + wc * 32 + j * 16;
            if (MODE == 0) {
                int b2 = gm >> 11, s = gm & 2047, h2 = gn >> 7, d = gn & 127;
                float* p = g_q + (((size_t)(b2 * NQ_ + h2)) * S_LEN + s) * HD_ + d;
                wmma::store_matrix_sync(p, acc[i][j], HD_, wmma::mem_row_major);
            } else if (MODE == 1) {
                int b2 = gm >> 11, s = gm & 2047;
                if (gn < NKV_ * HD_) {           // K head
                    int h2 = gn >> 7, d = gn & 127;
                    float* p = g_k + (((size_t)(b2 * NKV_ + h2)) * S_LEN + s) * HD_ + d;
                    wmma::store_matrix_sync(p, acc[i][j], HD_, wmma::mem_row_major);
                } else {                         // V head, store transposed [HD,S]
                    int nn = gn - NKV_ * HD_;
                    int h2 = nn >> 7, d = nn & 127;
                    float* p = g_vt + (((size_t)(b2 * NKV_ + h2)) * HD_ + d) * S_LEN + s;
                    wmma::store_matrix_sync(p, acc[i][j], S_LEN, wmma::mem_col_major);
                }
            } else if (MODE == 2) {
                #pragma unroll
                for (int e = 0; e < acc[i][j].num_elements; e++)
                    acc[i][j].x[e] *= 0.08838834764831845f;    // 1/sqrt(128)
                float* p = g_scores + (size_t)z * S_LEN * S_LEN + (size_t)gm * S_LEN + gn;
                wmma::store_matrix_sync(p, acc[i][j], S_LEN, wmma::mem_row_major);
            } else if (MODE == 3) {
                float* p = g_attn + ((size_t)bb * S_LEN + gm) * (NQ_ * HD_) + hh * HD_ + gn;
                wmma::store_matrix_sync(p, acc[i][j], NQ_ * HD_, wmma::mem_row_major);
            } else { // MODE 4
                float* p = Cext + (size_t)gm * HID_ + gn;
                wmma::store_matrix_sync(p, acc[i][j], HID_, wmma::mem_row_major);
            }
        }
    }
}

// ---------------------------------------------------------------------------
// RoPE: in-place on g_q (32 heads) and g_k (8 heads).
// cos/sin tables are broadcast over (B,H) -> read [s,d] of head 0, batch 0.
// ---------------------------------------------------------------------------
__global__ void __launch_bounds__(256)
rope_kernel(const float* __restrict__ cosp, const float* __restrict__ sinp)
{
    const int s  = blockIdx.x * blockDim.y + threadIdx.y;
    const int bh = blockIdx.y;
    const int hh = bh % (NQ_ + NKV_);
    const int b  = bh / (NQ_ + NKV_);
    float* base;
    if (hh < NQ_) base = g_q + (((size_t)(b * NQ_ + hh)) * S_LEN + s) * HD_;
    else          base = g_k + (((size_t)(b * NKV_ + (hh - NQ_))) * S_LEN + s) * HD_;

    const int d = threadIdx.x;     // 0..63
    const float c1 = cosp[(size_t)s * HD_ + d];
    const float c2 = cosp[(size_t)s * HD_ + d + 64];
    const float s1 = sinp[(size_t)s * HD_ + d];
    const float s2 = sinp[(size_t)s * HD_ + d + 64];
    const float x1 = base[d], x2 = base[d + 64];
    base[d]      = x1 * c1 - x2 * s1;
    base[d + 64] = x2 * c2 + x1 * s2;
}

// ---------------------------------------------------------------------------
// Causal row softmax over g_scores, in place. Row (z,i): valid j in [0,i].
// Also zero-fills j in (i, roundup128(i+1)) so the PV GEMM's tile-aligned
// K-loop reads exact zeros.
// ---------------------------------------------------------------------------
__global__ void __launch_bounds__(256)
softmax_kernel()
{
    const int i = blockIdx.x;
    const int z = blockIdx.y;
    float* row = g_scores + ((size_t)z * S_LEN + i) * S_LEN;
    const int len = i + 1;
    const int tid = threadIdx.x;

    float rv[8];
    int cnt = 0;
    float lmax = -1e30f;
    for (int j = tid; j < len; j += 256) { rv[cnt] = row[j]; lmax = fmaxf(lmax, rv[cnt]); cnt++; }

    __shared__ float red[8];
    #pragma unroll
    for (int o = 16; o > 0; o >>= 1) lmax = fmaxf(lmax, __shfl_xor_sync(0xffffffffu, lmax, o));
    if ((tid & 31) == 0) red[tid >> 5] = lmax;
    __syncthreads();
    float m = red[0];
    #pragma unroll
    for (int k = 1; k < 8; k++) m = fmaxf(m, red[k]);
    __syncthreads();

    float lsum = 0.0f;
    for (int k = 0; k < cnt; k++) { rv[k] = __expf(rv[k] - m); lsum += rv[k]; }
    #pragma unroll
    for (int o = 16; o > 0; o >>= 1) lsum += __shfl_xor_sync(0xffffffffu, lsum, o);
    if ((tid & 31) == 0) red[tid >> 5] = lsum;
    __syncthreads();
    float ssum = 0.0f;
    #pragma unroll
    for (int k = 0; k < 8; k++) ssum += red[k];
    const float inv = 1.0f / ssum;

    cnt = 0;
    for (int j = tid; j < len; j += 256) row[j] = rv[cnt++] * inv;

    const int jend = ((i >> 7) + 1) << 7;
    for (int j = len + tid; j < jend; j += 256) row[j] = 0.0f;
}

// ---------------------------------------------------------------------------
// kernel_launch
// Inputs: 0:x 1:cos 2:sin 3:attention_mask(unused; causal) 4:Wq 5:Wkv 6:Wo
// ---------------------------------------------------------------------------
extern "C" void kernel_launch(void* const* d_in, const int* in_sizes, int n_in,
                              void* d_out, int out_size)
{
    const float* x    = (const float*)d_in[0];
    const float* cosp = (const float*)d_in[1];
    const float* sinp = (const float*)d_in[2];
    const float* Wq   = (const float*)d_in[4];
    const float* Wkv  = (const float*)d_in[5];
    const float* Wo   = (const float*)d_in[6];
    float* out = (float*)d_out;

    cudaFuncSetAttribute(gemm_tf32<0>, cudaFuncAttributeMaxDynamicSharedMemorySize, SMEM_BYTES);
    cudaFuncSetAttribute(gemm_tf32<1>, cudaFuncAttributeMaxDynamicSharedMemorySize, SMEM_BYTES);
    cudaFuncSetAttribute(gemm_tf32<2>, cudaFuncAttributeMaxDynamicSharedMemorySize, SMEM_BYTES);
    cudaFuncSetAttribute(gemm_tf32<3>, cudaFuncAttributeMaxDynamicSharedMemorySize, SMEM_BYTES);
    cudaFuncSetAttribute(gemm_tf32<4>, cudaFuncAttributeMaxDynamicSharedMemorySize, SMEM_BYTES);

    // 1) Q projection: [4096,4096] x Wq^T -> g_q scatter
    gemm_tf32<0><<<dim3(HID_ / BN, (BATCH * S_LEN) / BM), 256, SMEM_BYTES>>>(x, Wq, nullptr, HID_);
    // 2) KV projection: [4096,4096] x Wkv^T -> g_k / g_vt scatter
    gemm_tf32<1><<<dim3((2 * NKV_ * HD_) / BN, (BATCH * S_LEN) / BM), 256, SMEM_BYTES>>>(x, Wkv, nullptr, HID_);
    // 3) RoPE in place on Q and K
    rope_kernel<<<dim3(S_LEN / 4, BATCH * (NQ_ + NKV_)), dim3(64, 4)>>>(cosp, sinp);
    // 4) scores = Q K^T * scale (lower-triangular tiles only: 16*17/2 = 136)
    gemm_tf32<2><<<dim3(136, 1, BATCH * NQ_), 256, SMEM_BYTES>>>(nullptr, nullptr, nullptr, HD_);
    // 5) causal softmax rows
    softmax_kernel<<<dim3(S_LEN, BATCH * NQ_), 256>>>();
    // 6) O = P V (K-limited per causal tile row)
    gemm_tf32<3><<<dim3(HD_ / BN, S_LEN / BM, BATCH * NQ_), 256, SMEM_BYTES>>>(nullptr, nullptr, nullptr, S_LEN);
    // 7) output projection -> d_out
    gemm_tf32<4><<<dim3(HID_ / BN, (BATCH * S_LEN) / BM), 256, SMEM_BYTES>>>(nullptr, Wo, out, HID_);
}

// round 3
// speedup vs baseline: 1.1298x; 1.1298x over previous
#include <cuda_runtime.h>
#include <mma.h>
#include <cstdint>

using namespace nvcuda;

// Problem constants
#define S_LEN 2048
#define HID_  4096
#define NQ_   32
#define NKV_  8
#define HD_   128
#define BATCH 2
#define GRP   (NQ_ / NKV_)   // 4 q-heads per kv-head

// ---------------------------------------------------------------------------
// Device scratch (static: no allocations allowed)
// ---------------------------------------------------------------------------
__device__ float g_q [(size_t)BATCH * NQ_  * S_LEN * HD_];   // [B,NQ,S,HD]   64 MB
__device__ float g_k [(size_t)BATCH * NKV_ * S_LEN * HD_];   // [B,NKV,S,HD]  16 MB
__device__ float g_vt[(size_t)BATCH * NKV_ * HD_ * S_LEN];   // [B,NKV,HD,S]  16 MB (V transposed)
__device__ float g_scores[268435456];                        // [B*NQ,S,S]     1 GB
__device__ float g_attn[(size_t)BATCH * S_LEN * NQ_ * HD_];  // [B,S,NQ*HD]   64 MB
// TF32-pre-rounded copies of the inputs (rounding is done once, outside GEMMs)
__device__ float g_xr  [(size_t)BATCH * S_LEN * HID_];       // 32 MB
__device__ float g_wqr [(size_t)HID_ * HID_];                // 64 MB
__device__ float g_wkvr[(size_t)2 * NKV_ * HD_ * HID_];      // 32 MB
__device__ float g_wor [(size_t)HID_ * HID_];                // 64 MB

__device__ __forceinline__ float tf32r(float v) { return wmma::__float_to_tf32(v); }

// ---------------------------------------------------------------------------
// GEMM config: C[M,N] = A[M,K] * B[N,K]^T   (tf32 tensor cores)
// Block tile 128x128, K-tile 32, 256 threads (8 warps, 2x4), warp tile 64x32
// All operands are pre-rounded to TF32, so no in-loop conversion is needed.
// ---------------------------------------------------------------------------
constexpr int BM = 128, BN = 128, BK = 32;
constexpr int LDS = BK + 4;                 // skew: 36 floats (144B rows, 16B aligned)
constexpr int SMEM_BYTES = (2 * BM * LDS + 2 * BN * LDS) * 4;   // 73728

__device__ __forceinline__ void cp_async16(float* smem_dst, const float* gsrc) {
    uint32_t d = (uint32_t)__cvta_generic_to_shared(smem_dst);
    asm volatile("cp.async.cg.shared.global [%0], [%1], 16;\n" :: "r"(d), "l"(gsrc));
}
__device__ __forceinline__ void cp_commit() { asm volatile("cp.async.commit_group;\n"); }
__device__ __forceinline__ void cp_wait0()  { asm volatile("cp.async.wait_group 0;\n"); }

// MODE 0: Q-proj   A=xr                  B=Wqr             -> scatter g_q
// MODE 1: KV-proj  A=xr                  B=Wkvr            -> scatter g_k / g_vt (V transposed)
// MODE 2: scores   A=g_q head slice      B=g_k head slice  -> g_scores (causal tiles, scaled)
// MODE 3: PV       A=g_scores head slice B=g_vt head slice -> g_attn
// MODE 4: O-proj   A=g_attn              B=Wor             -> d_out
template<int MODE>
__global__ void __launch_bounds__(256, 2)
gemm_tf32(float* __restrict__ Cext, int Kdim)
{
    extern __shared__ float smem[];
    float* As = smem;                      // 2 * BM * LDS
    float* Bs = smem + 2 * BM * LDS;       // 2 * BN * LDS

    int mtile = blockIdx.y;
    int ntile = blockIdx.x;

    if (MODE == 2) {
        // Linearized lower-triangular tile index: blockIdx.x in [0,136)
        int t = blockIdx.x;
        int it = 0;
        while (t >= it + 1) { t -= it + 1; it++; }
        mtile = it; ntile = t;
    }

    const int m0 = mtile * BM;
    const int n0 = ntile * BN;

    const float* Ap; const float* Bp;
    int lda, ldb;
    int z = 0, bb = 0, hh = 0;

    if (MODE == 0) { Ap = g_xr; Bp = g_wqr; lda = HID_; ldb = HID_; }
    else if (MODE == 1) { Ap = g_xr; Bp = g_wkvr; lda = HID_; ldb = HID_; }
    else if (MODE == 2) {
        z = blockIdx.z; bb = z / NQ_; hh = z % NQ_;
        int kvh = hh / GRP;
        Ap = g_q + (size_t)z * S_LEN * HD_;                    lda = HD_;
        Bp = g_k + (size_t)(bb * NKV_ + kvh) * S_LEN * HD_;    ldb = HD_;
    }
    else if (MODE == 3) {
        z = blockIdx.z; bb = z / NQ_; hh = z % NQ_;
        int kvh = hh / GRP;
        Ap = g_scores + (size_t)z * S_LEN * S_LEN;             lda = S_LEN;
        Bp = g_vt + (size_t)(bb * NKV_ + kvh) * HD_ * S_LEN;   ldb = S_LEN;
        Kdim = min(Kdim, (mtile + 1) * BM);                    // causal K-limit
    }
    else { // MODE 4
        Ap = g_attn; Bp = g_wor; lda = HID_; ldb = HID_;
    }

    const int tid  = threadIdx.x;
    const int warp = tid >> 5;
    const int wr   = warp >> 2;    // 0..1
    const int wc   = warp & 3;     // 0..3

    wmma::fragment<wmma::accumulator, 16, 16, 8, float> acc[4][2];
    #pragma unroll
    for (int i = 0; i < 4; i++)
        #pragma unroll
        for (int j = 0; j < 2; j++)
            wmma::fill_fragment(acc[i][j], 0.0f);

    auto loadA = [&](int t, int buf) {
        const float* src = Ap + (size_t)m0 * lda + t * BK;
        float* dst = As + buf * BM * LDS;
        #pragma unroll
        for (int i = 0; i < 4; i++) {
            int idx = tid + i * 256;
            int row = idx >> 3, seg = idx & 7;
            cp_async16(dst + row * LDS + seg * 4, src + (size_t)row * lda + seg * 4);
        }
    };
    auto loadB = [&](int t, int buf) {
        const float* src = Bp + (size_t)n0 * ldb + t * BK;
        float* dst = Bs + buf * BN * LDS;
        #pragma unroll
        for (int i = 0; i < 4; i++) {
            int idx = tid + i * 256;
            int row = idx >> 3, seg = idx & 7;
            cp_async16(dst + row * LDS + seg * 4, src + (size_t)row * ldb + seg * 4);
        }
    };

    const int T = Kdim / BK;
    loadA(0, 0); loadB(0, 0); cp_commit();

    for (int t = 0; t < T; t++) {
        cp_wait0();
        __syncthreads();
        if (t + 1 < T) { loadA(t + 1, (t + 1) & 1); loadB(t + 1, (t + 1) & 1); cp_commit(); }

        const float* Ab = As + (t & 1) * BM * LDS;
        const float* Bb = Bs + (t & 1) * BN * LDS;

        #pragma unroll
        for (int kk = 0; kk < BK / 8; kk++) {
            wmma::fragment<wmma::matrix_a, 16, 16, 8, wmma::precision::tf32, wmma::row_major> af[4];
            wmma::fragment<wmma::matrix_b, 16, 16, 8, wmma::precision::tf32, wmma::col_major> bf[2];
            #pragma unroll
            for (int i = 0; i < 4; i++)
                wmma::load_matrix_sync(af[i], Ab + (wr * 64 + i * 16) * LDS + kk * 8, LDS);
            #pragma unroll
            for (int j = 0; j < 2; j++)
                wmma::load_matrix_sync(bf[j], Bb + (wc * 32 + j * 16) * LDS + kk * 8, LDS);
            // Operands are pre-rounded TF32 values: no conversion needed.
            #pragma unroll
            for (int i = 0; i < 4; i++)
                #pragma unroll
                for (int j = 0; j < 2; j++)
                    wmma::mma_sync(acc[i][j], af[i], bf[j], acc[i][j]);
        }
        __syncthreads();
    }

    // -------------------- epilogue (per-mode scatter) --------------------
    #pragma unroll
    for (int i = 0; i < 4; i++) {
        #pragma unroll
        for (int j = 0; j < 2; j++) {
            const int gm = m0 + wr * 64 + i * 16;
            const int gn = n0 + wc * 32 + j * 16;
            if (MODE == 0) {
                // rope re-rounds these; store raw
                int b2 = gm >> 11, s = gm & 2047, h2 = gn >> 7, d = gn & 127;
                float* p = g_q + (((size_t)(b2 * NQ_ + h2)) * S_LEN + s) * HD_ + d;
                wmma::store_matrix_sync(p, acc[i][j], HD_, wmma::mem_row_major);
            } else if (MODE == 1) {
                int b2 = gm >> 11, s = gm & 2047;
                if (gn < NKV_ * HD_) {           // K head (rope re-rounds; store raw)
                    int h2 = gn >> 7, d = gn & 127;
                    float* p = g_k + (((size_t)(b2 * NKV_ + h2)) * S_LEN + s) * HD_ + d;
                    wmma::store_matrix_sync(p, acc[i][j], HD_, wmma::mem_row_major);
                } else {                         // V head: round + store transposed [HD,S]
                    #pragma unroll
                    for (int e = 0; e < acc[i][j].num_elements; e++)
                        acc[i][j].x[e] = tf32r(acc[i][j].x[e]);
                    int nn = gn - NKV_ * HD_;
                    int h2 = nn >> 7, d = nn & 127;
                    float* p = g_vt + (((size_t)(b2 * NKV_ + h2)) * HD_ + d) * S_LEN + s;
                    wmma::store_matrix_sync(p, acc[i][j], S_LEN, wmma::mem_col_major);
                }
            } else if (MODE == 2) {
                #pragma unroll
                for (int e = 0; e < acc[i][j].num_elements; e++)
                    acc[i][j].x[e] *= 0.08838834764831845f;    // 1/sqrt(128)
                float* p = g_scores + (size_t)z * S_LEN * S_LEN + (size_t)gm * S_LEN + gn;
                wmma::store_matrix_sync(p, acc[i][j], S_LEN, wmma::mem_row_major);
            } else if (MODE == 3) {
                #pragma unroll
                for (int e = 0; e < acc[i][j].num_elements; e++)
                    acc[i][j].x[e] = tf32r(acc[i][j].x[e]);
                float* p = g_attn + ((size_t)bb * S_LEN + gm) * (NQ_ * HD_) + hh * HD_ + gn;
                wmma::store_matrix_sync(p, acc[i][j], NQ_ * HD_, wmma::mem_row_major);
            } else { // MODE 4 -> final output, full precision
                float* p = Cext + (size_t)gm * HID_ + gn;
                wmma::store_matrix_sync(p, acc[i][j], HID_, wmma::mem_row_major);
            }
        }
    }
}

// ---------------------------------------------------------------------------
// TF32 pre-rounding pass (vectorized): dst[i] = round_tf32(src[i])
// ---------------------------------------------------------------------------
__global__ void __launch_bounds__(256)
round_kernel(const float4* __restrict__ src, float4* __restrict__ dst, int n4)
{
    int i = blockIdx.x * blockDim.x + threadIdx.x;
    if (i < n4) {
        float4 v = src[i];
        v.x = tf32r(v.x); v.y = tf32r(v.y); v.z = tf32r(v.z); v.w = tf32r(v.w);
        dst[i] = v;
    }
}

// ---------------------------------------------------------------------------
// RoPE: in-place on g_q (32 heads) and g_k (8 heads), writes TF32-rounded.
// cos/sin tables are broadcast over (B,H) -> read [s,d] of head 0, batch 0.
// ---------------------------------------------------------------------------
__global__ void __launch_bounds__(256)
rope_kernel(const float* __restrict__ cosp, const float* __restrict__ sinp)
{
    const int s  = blockIdx.x * blockDim.y + threadIdx.y;
    const int bh = blockIdx.y;
    const int hh = bh % (NQ_ + NKV_);
    const int b  = bh / (NQ_ + NKV_);
    float* base;
    if (hh < NQ_) base = g_q + (((size_t)(b * NQ_ + hh)) * S_LEN + s) * HD_;
    else          base = g_k + (((size_t)(b * NKV_ + (hh - NQ_))) * S_LEN + s) * HD_;

    const int d = threadIdx.x;     // 0..63
    const float c1 = cosp[(size_t)s * HD_ + d];
    const float c2 = cosp[(size_t)s * HD_ + d + 64];
    const float s1 = sinp[(size_t)s * HD_ + d];
    const float s2 = sinp[(size_t)s * HD_ + d + 64];
    const float x1 = base[d], x2 = base[d + 64];
    base[d]      = tf32r(x1 * c1 - x2 * s1);
    base[d + 64] = tf32r(x2 * c2 + x1 * s2);
}

// ---------------------------------------------------------------------------
// Causal row softmax over g_scores, in place; writes TF32-rounded probs.
// Also zero-fills j in (i, roundup128(i+1)) so the PV GEMM's tile-aligned
// K-loop reads exact zeros.
// ---------------------------------------------------------------------------
__global__ void __launch_bounds__(256)
softmax_kernel()
{
    const int i = blockIdx.x;
    const int z = blockIdx.y;
    float* row = g_scores + ((size_t)z * S_LEN + i) * S_LEN;
    const int len = i + 1;
    const int tid = threadIdx.x;

    float rv[8];
    int cnt = 0;
    float lmax = -1e30f;
    for (int j = tid; j < len; j += 256) { rv[cnt] = row[j]; lmax = fmaxf(lmax, rv[cnt]); cnt++; }

    __shared__ float red[8];
    #pragma unroll
    for (int o = 16; o > 0; o >>= 1) lmax = fmaxf(lmax, __shfl_xor_sync(0xffffffffu, lmax, o));
    if ((tid & 31) == 0) red[tid >> 5] = lmax;
    __syncthreads();
    float m = red[0];
    #pragma unroll
    for (int k = 1; k < 8; k++) m = fmaxf(m, red[k]);
    __syncthreads();

    float lsum = 0.0f;
    for (int k = 0; k < cnt; k++) { rv[k] = __expf(rv[k] - m); lsum += rv[k]; }
    #pragma unroll
    for (int o = 16; o > 0; o >>= 1) lsum += __shfl_xor_sync(0xffffffffu, lsum, o);
    if ((tid & 31) == 0) red[tid >> 5] = lsum;
    __syncthreads();
    float ssum = 0.0f;
    #pragma unroll
    for (int k = 0; k < 8; k++) ssum += red[k];
    const float inv = 1.0f / ssum;

    cnt = 0;
    for (int j = tid; j < len; j += 256) row[j] = tf32r(rv[cnt++] * inv);

    const int jend = ((i >> 7) + 1) << 7;
    for (int j = len + tid; j < jend; j += 256) row[j] = 0.0f;
}

// ---------------------------------------------------------------------------
// kernel_launch
// Inputs: 0:x 1:cos 2:sin 3:attention_mask(unused; causal) 4:Wq 5:Wkv 6:Wo
// ---------------------------------------------------------------------------
extern "C" void kernel_launch(void* const* d_in, const int* in_sizes, int n_in,
                              void* d_out, int out_size)
{
    const float* x    = (const float*)d_in[0];
    const float* cosp = (const float*)d_in[1];
    const float* sinp = (const float*)d_in[2];
    const float* Wq   = (const float*)d_in[4];
    const float* Wkv  = (const float*)d_in[5];
    const float* Wo   = (const float*)d_in[6];
    float* out = (float*)d_out;

    cudaFuncSetAttribute(gemm_tf32<0>, cudaFuncAttributeMaxDynamicSharedMemorySize, SMEM_BYTES);
    cudaFuncSetAttribute(gemm_tf32<1>, cudaFuncAttributeMaxDynamicSharedMemorySize, SMEM_BYTES);
    cudaFuncSetAttribute(gemm_tf32<2>, cudaFuncAttributeMaxDynamicSharedMemorySize, SMEM_BYTES);
    cudaFuncSetAttribute(gemm_tf32<3>, cudaFuncAttributeMaxDynamicSharedMemorySize, SMEM_BYTES);
    cudaFuncSetAttribute(gemm_tf32<4>, cudaFuncAttributeMaxDynamicSharedMemorySize, SMEM_BYTES);

    // 0) TF32 pre-rounding of inputs into scratch copies
    {
        float* g_xr_p;  cudaGetSymbolAddress((void**)&g_xr_p,  g_xr);
        float* g_wqr_p; cudaGetSymbolAddress((void**)&g_wqr_p, g_wqr);
        float* g_wkvr_p;cudaGetSymbolAddress((void**)&g_wkvr_p,g_wkvr);
        float* g_wor_p; cudaGetSymbolAddress((void**)&g_wor_p, g_wor);
        int n4x  = (BATCH * S_LEN * HID_) / 4;
        int n4q  = (HID_ * HID_) / 4;
        int n4kv = (2 * NKV_ * HD_ * HID_) / 4;
        round_kernel<<<(n4x  + 255) / 256, 256>>>((const float4*)x,   (float4*)g_xr_p,  n4x);
        round_kernel<<<(n4q  + 255) / 256, 256>>>((const float4*)Wq,  (float4*)g_wqr_p, n4q);
        round_kernel<<<(n4kv + 255) / 256, 256>>>((const float4*)Wkv, (float4*)g_wkvr_p,n4kv);
        round_kernel<<<(n4q  + 255) / 256, 256>>>((const float4*)Wo,  (float4*)g_wor_p, n4q);
    }

    // 1) Q projection -> g_q scatter
    gemm_tf32<0><<<dim3(HID_ / BN, (BATCH * S_LEN) / BM), 256, SMEM_BYTES>>>(nullptr, HID_);
    // 2) KV projection -> g_k / g_vt scatter
    gemm_tf32<1><<<dim3((2 * NKV_ * HD_) / BN, (BATCH * S_LEN) / BM), 256, SMEM_BYTES>>>(nullptr, HID_);
    // 3) RoPE in place on Q and K (writes TF32-rounded)
    rope_kernel<<<dim3(S_LEN / 4, BATCH * (NQ_ + NKV_)), dim3(64, 4)>>>(cosp, sinp);
    // 4) scores = Q K^T * scale (lower-triangular tiles only: 16*17/2 = 136)
    gemm_tf32<2><<<dim3(136, 1, BATCH * NQ_), 256, SMEM_BYTES>>>(nullptr, HD_);
    // 5) causal softmax rows (writes TF32-rounded probs)
    softmax_kernel<<<dim3(S_LEN, BATCH * NQ_), 256>>>();
    // 6) O = P V (K-limited per causal tile row)
    gemm_tf32<3><<<dim3(HD_ / BN, S_LEN / BM, BATCH * NQ_), 256, SMEM_BYTES>>>(nullptr, S_LEN);
    // 7) output projection -> d_out
    gemm_tf32<4><<<dim3(HID_ / BN, (BATCH * S_LEN) / BM), 256, SMEM_BYTES>>>(out, HID_);
}